// round 12
// baseline (speedup 1.0000x reference)
#include <cuda_runtime.h>

// upfirdn2d(up=2, down=1, pad=5), 12x12 separable K = h h^T, via fma.rn.f32x2.
// Proven skeleton (R8, 114us): 128x64 tile, 256 threads, parity-pair outputs,
// broadcast-input FFMA2, sliding register windows, idx-based load loop.
// R11: two column-halves share one half-size s_tmp -> smem ~20KB -> 8 blocks/SM
// (vs 7), shorter phases, more independent barrier domains per SM.

#define IMG_H 256
#define IMG_W 256
#define OUT_H 511
#define OUT_W 511
#define TILE_W 128
#define TILE_H 64
#define IN_W  69      // input cols per 128-wide output tile
#define IN_H  37      // input rows per 64-tall output tile
#define SPITCH 69     // stride mod 32 = 5 -> conflict-free s_in column reads
#define HP2   33      // float2 pitch for half-tile tmp rows (66 floats)
#define NTHR  256

__device__ __forceinline__ float2 ffma2(float2 a, float2 b, float2 c) {
    float2 d;
    asm("fma.rn.f32x2 %0, %1, %2, %3;"
        : "=l"(*reinterpret_cast<unsigned long long*>(&d))
        : "l"(*reinterpret_cast<unsigned long long*>(&a)),
          "l"(*reinterpret_cast<unsigned long long*>(&b)),
          "l"(*reinterpret_cast<unsigned long long*>(&c)));
    return d;
}

__device__ __forceinline__ float2 fmul2(float2 a, float2 b) {
    float2 d;
    asm("mul.rn.f32x2 %0, %1, %2;"
        : "=l"(*reinterpret_cast<unsigned long long*>(&d))
        : "l"(*reinterpret_cast<unsigned long long*>(&a)),
          "l"(*reinterpret_cast<unsigned long long*>(&b)));
    return d;
}

__device__ __forceinline__ float2 bcast(float w) { return make_float2(w, w); }

__global__ __launch_bounds__(NTHR)
void lpf_up2_kernel(const float* __restrict__ x,
                    const float* __restrict__ K,
                    float* __restrict__ out) {
    __shared__ float  s_in[IN_H * SPITCH];   // 37 x 69 input tile (10.2 KB)
    __shared__ float2 s_tmp[IN_H * HP2];     // half-tile horiz result (9.8 KB)
    __shared__ float2 s_c[6];                // (h_even_tap[t], h_odd_tap[t])

    const int tid = threadIdx.x;
    const int img = blockIdx.z;
    const int ox0 = blockIdx.x * TILE_W;     // even
    const int oy0 = blockIdx.y * TILE_H;     // even
    const int mx0 = (ox0 >> 1) - 2;
    const int my0 = (oy0 >> 1) - 2;

    // Recover separable h from K row 5: h[j] = K[5][j] / sqrt(K[5][5]).
    // Sign ambiguity cancels (all taps are h*h products).
    if (tid < 6) {
        float s = rsqrtf(K[5 * 12 + 5]);
        s_c[tid] = make_float2(K[5 * 12 + (10 - 2 * tid)] * s,
                               K[5 * 12 + (11 - 2 * tid)] * s);
    }

    // ---- Load input tile (independent iterations -> high MLP) ----
    const float* __restrict__ xin = x + (size_t)img * (IMG_H * IMG_W);
    #pragma unroll
    for (int idx = tid; idx < IN_H * IN_W; idx += NTHR) {
        int r = idx / IN_W;
        int c = idx - r * IN_W;
        int gy = my0 + r;
        int gx = mx0 + c;
        float v = 0.0f;
        if ((unsigned)gy < IMG_H && (unsigned)gx < IMG_W)
            v = xin[gy * IMG_W + gx];
        s_in[r * SPITCH + c] = v;
    }
    __syncthreads();

    const float2 c0 = s_c[0], c1 = s_c[1], c2 = s_c[2],
                 c3 = s_c[3], c4 = s_c[4], c5 = s_c[5];

    float* __restrict__ o_img = out + (size_t)img * ((size_t)OUT_H * OUT_W);

    // ---- Two column halves: horiz (64 out cols) -> sync -> vert -> sync ----
    #pragma unroll
    for (int half = 0; half < 2; half++) {
        const int cbase = half * 32;         // input-col / pair offset of half

        // Horizontal: 37 rows x 8 groups of 4 pairs = 296 tasks.
        // tmp[r][k] (pair k in 0..31) = sum_t c[t]*s_in[r][cbase+k+t]
        #pragma unroll
        for (int tt = 0; tt < 2; tt++) {
            int t = tid + NTHR * tt;
            if (t < IN_H * 8) {
                int kg = t / IN_H;            // 0..7
                int r  = t - kg * IN_H;       // 0..36
                int k0 = kg * 4;
                const float* row = s_in + r * SPITCH + cbase + k0;
                float2* trow = s_tmp + r * HP2 + k0;
                float2 p0 = bcast(row[0]), p1 = bcast(row[1]),
                       p2 = bcast(row[2]), p3 = bcast(row[3]),
                       p4 = bcast(row[4]), p5 = bcast(row[5]);
                #pragma unroll
                for (int j = 0; j < 4; j++) {
                    float2 acc = fmul2(p0, c0);
                    acc = ffma2(p1, c1, acc);
                    acc = ffma2(p2, c2, acc);
                    acc = ffma2(p3, c3, acc);
                    acc = ffma2(p4, c4, acc);
                    acc = ffma2(p5, c5, acc);
                    trow[j] = acc;
                    p0 = p1; p1 = p2; p2 = p3; p3 = p4; p4 = p5;
                    if (j < 3) p5 = bcast(row[j + 6]);  // max col 28+3+6+32=69-1
                }
            }
        }
        __syncthreads();

        // Vertical: 64 cols x 4 groups of 8 row-pairs = 256 threads exactly.
        {
            const int ox = tid & 63;
            const int j0 = (tid >> 6) * 8;   // 0,8,16,24
            const float* tcol =
                reinterpret_cast<const float*>(s_tmp) + j0 * (HP2 * 2) + ox;
            float2 v0 = bcast(tcol[0 * (HP2 * 2)]);
            float2 v1 = bcast(tcol[1 * (HP2 * 2)]);
            float2 v2 = bcast(tcol[2 * (HP2 * 2)]);
            float2 v3 = bcast(tcol[3 * (HP2 * 2)]);
            float2 v4 = bcast(tcol[4 * (HP2 * 2)]);
            float2 v5 = bcast(tcol[5 * (HP2 * 2)]);

            const int  gox = ox0 + 2 * cbase + ox;
            const bool xok = (gox < OUT_W);
            float* __restrict__ p =
                o_img + (size_t)(oy0 + 2 * j0) * OUT_W + gox;
            const bool lastgrp = (oy0 + 2 * j0 == 496);   // j=7 would hit row 511

            #pragma unroll
            for (int j = 0; j < 8; j++) {
                float2 acc = fmul2(v0, c0);
                acc = ffma2(v1, c1, acc);
                acc = ffma2(v2, c2, acc);
                acc = ffma2(v3, c3, acc);
                acc = ffma2(v4, c4, acc);
                acc = ffma2(v5, c5, acc);
                if (xok) {
                    p[(size_t)(2 * j) * OUT_W] = acc.x;   // even row <= 510
                    if (!lastgrp || j < 7)                 // skip row 511
                        p[(size_t)(2 * j + 1) * OUT_W] = acc.y;
                }
                v0 = v1; v1 = v2; v2 = v3; v3 = v4; v4 = v5;
                if (j < 7) v5 = bcast(tcol[(j + 6) * (HP2 * 2)]); // row <= 36
            }
        }
        if (half == 0) __syncthreads();      // protect s_tmp before half 2
    }
}

extern "C" void kernel_launch(void* const* d_in, const int* in_sizes, int n_in,
                              void* d_out, int out_size) {
    const float* x = (const float*)d_in[0];   // [8,64,256,256] f32
    const float* K = (const float*)d_in[1];   // [12,12] f32
    float* out = (float*)d_out;               // [8,64,511,511] f32

    int imgs = in_sizes[0] / (IMG_H * IMG_W); // 512
    dim3 grid((OUT_W + TILE_W - 1) / TILE_W,  // 4
              (OUT_H + TILE_H - 1) / TILE_H,  // 8
              imgs);                          // 512
    lpf_up2_kernel<<<grid, NTHR>>>(x, K, out);
}

// round 13
// speedup vs baseline: 1.2058x; 1.2058x over previous
#include <cuda_runtime.h>
#include <cstdint>

// upfirdn2d(up=2, down=1, pad=5), 12x12 separable K = h h^T, via fma.rn.f32x2.
// R8 skeleton (best: 114us): 128x64 tile, 256 threads, parity-pair outputs,
// broadcast-input FFMA2, sliding register windows.
// R12: each block processes 4 y-tiles with cp.async double-buffered input
// loads -> tile t+1's DRAM reads overlap tile t's compute/store phases.

#define IMG_H 256
#define IMG_W 256
#define OUT_H 511
#define OUT_W 511
#define TILE_W 128
#define TILE_H 64
#define IN_W  69      // input cols per 128-wide output tile
#define IN_H  37      // input rows per 64-tall output tile
#define SPITCH 69     // stride mod 32 = 5 -> conflict-free s_in column reads
#define TP2   65      // float2 pitch for tmp rows (130 floats)
#define NTHR  256
#define TILES_Y 4     // y-tiles per block (8 total / grid.y=2)

__device__ __forceinline__ float2 ffma2(float2 a, float2 b, float2 c) {
    float2 d;
    asm("fma.rn.f32x2 %0, %1, %2, %3;"
        : "=l"(*reinterpret_cast<unsigned long long*>(&d))
        : "l"(*reinterpret_cast<unsigned long long*>(&a)),
          "l"(*reinterpret_cast<unsigned long long*>(&b)),
          "l"(*reinterpret_cast<unsigned long long*>(&c)));
    return d;
}

__device__ __forceinline__ float2 fmul2(float2 a, float2 b) {
    float2 d;
    asm("mul.rn.f32x2 %0, %1, %2;"
        : "=l"(*reinterpret_cast<unsigned long long*>(&d))
        : "l"(*reinterpret_cast<unsigned long long*>(&a)),
          "l"(*reinterpret_cast<unsigned long long*>(&b)));
    return d;
}

__device__ __forceinline__ float2 bcast(float w) { return make_float2(w, w); }

// 4-byte cp.async with zero-fill when out of bounds (src-size = 0).
__device__ __forceinline__ void cp4(uint32_t daddr, const float* g, bool ok) {
    int sz = ok ? 4 : 0;
    asm volatile("cp.async.ca.shared.global [%0], [%1], 4, %2;"
                 :: "r"(daddr), "l"(g), "r"(sz));
}

// Issue all cp.async ops for one input tile into the smem buffer at s_addr.
__device__ __forceinline__ void issue_tile_load(uint32_t s_addr,
                                                const float* __restrict__ xin,
                                                int my0, int mx0) {
    const int tid = threadIdx.x;
    #pragma unroll
    for (int it = 0; it < 10; it++) {
        int idx = tid + NTHR * it;
        if (idx < IN_H * IN_W) {
            int r = idx / IN_W;
            int c = idx - r * IN_W;
            int gy = my0 + r;
            int gx = mx0 + c;
            bool ok = ((unsigned)gy < IMG_H) && ((unsigned)gx < IMG_W);
            cp4(s_addr + (uint32_t)(r * SPITCH + c) * 4u,
                xin + gy * IMG_W + gx, ok);
        }
    }
    asm volatile("cp.async.commit_group;");
}

__global__ __launch_bounds__(NTHR)
void lpf_up2_kernel(const float* __restrict__ x,
                    const float* __restrict__ K,
                    float* __restrict__ out) {
    __shared__ float  s_in[2][IN_H * SPITCH];  // double-buffered input tiles
    __shared__ float2 s_tmp[IN_H * TP2];       // horiz result: 37 rows x 128 cols
    __shared__ float2 s_c[6];                  // (h_even_tap[t], h_odd_tap[t])

    const int tid = threadIdx.x;
    const int img = blockIdx.z;
    const int ox0 = blockIdx.x * TILE_W;       // even
    const int ty0 = blockIdx.y * TILES_Y;      // first y-tile index
    const int mx0 = (ox0 >> 1) - 2;

    // Recover separable h from K row 5: h[j] = K[5][j] / sqrt(K[5][5]).
    // Sign ambiguity cancels (all taps are h*h products).
    if (tid < 6) {
        float s = rsqrtf(K[5 * 12 + 5]);
        s_c[tid] = make_float2(K[5 * 12 + (10 - 2 * tid)] * s,
                               K[5 * 12 + (11 - 2 * tid)] * s);
    }

    const float* __restrict__ xin = x + (size_t)img * (IMG_H * IMG_W);
    float* __restrict__ o_img = out + (size_t)img * ((size_t)OUT_H * OUT_W);

    const uint32_t sa0 = (uint32_t)__cvta_generic_to_shared(&s_in[0][0]);
    const uint32_t sa1 = (uint32_t)__cvta_generic_to_shared(&s_in[1][0]);

    // Prologue: load tile 0 into buffer 0.
    issue_tile_load(sa0, xin, ((ty0 + 0) * TILE_H >> 1) - 2, mx0);

    #pragma unroll
    for (int t = 0; t < TILES_Y; t++) {
        const int b = t & 1;
        const int oy0 = (ty0 + t) * TILE_H;

        // Prefetch tile t+1 into the other buffer (safe: its last reader was
        // horiz(t-1), which finished before the trailing sync of iter t-1),
        // then wait for tile t's data (<=1 group pending).
        if (t + 1 < TILES_Y) {
            issue_tile_load(b ? sa0 : sa1, xin,
                            ((ty0 + t + 1) * TILE_H >> 1) - 2, mx0);
            asm volatile("cp.async.wait_group 1;");
        } else {
            asm volatile("cp.async.wait_group 0;");
        }
        __syncthreads();

        const float2 c0 = s_c[0], c1 = s_c[1], c2 = s_c[2],
                     c3 = s_c[3], c4 = s_c[4], c5 = s_c[5];
        const float* sin_b = &s_in[b][0];

        // ---- Horizontal pass: tmp[r][pair k] = sum_t c[t]*s_in[r][k+t] ----
        // 37 rows x 8 groups of 8 pairs = 296 tasks; threads 0..39 take 2nd slot.
        #pragma unroll
        for (int tt = 0; tt < 2; tt++) {
            int tk = tid + NTHR * tt;
            if (tk < IN_H * 8) {
                int kg = tk / IN_H;           // 0..7
                int r  = tk - kg * IN_H;      // 0..36
                int k0 = kg * 8;
                const float* row = sin_b + r * SPITCH + k0;
                float2* trow = s_tmp + r * TP2 + k0;
                float2 p0 = bcast(row[0]), p1 = bcast(row[1]),
                       p2 = bcast(row[2]), p3 = bcast(row[3]),
                       p4 = bcast(row[4]), p5 = bcast(row[5]);
                #pragma unroll
                for (int j = 0; j < 8; j++) {
                    float2 acc = fmul2(p0, c0);
                    acc = ffma2(p1, c1, acc);
                    acc = ffma2(p2, c2, acc);
                    acc = ffma2(p3, c3, acc);
                    acc = ffma2(p4, c4, acc);
                    acc = ffma2(p5, c5, acc);
                    trow[j] = acc;
                    p0 = p1; p1 = p2; p2 = p3; p3 = p4; p4 = p5;
                    if (j < 7) p5 = bcast(row[j + 6]);   // max col 56+7+6=68
                }
            }
        }
        __syncthreads();

        // ---- Vertical pass: out rows (2J,2J+1) = sum_t c[t]*tmp[J+t][ox] ----
        // 128 columns x 2 groups of 16 row-pairs.
        {
            const int ox = tid & 127;
            const int j0 = (tid >> 7) * 16;   // 0 or 16
            const float* tcol =
                reinterpret_cast<const float*>(s_tmp) + j0 * (TP2 * 2) + ox;
            float2 v0 = bcast(tcol[0 * (TP2 * 2)]);
            float2 v1 = bcast(tcol[1 * (TP2 * 2)]);
            float2 v2 = bcast(tcol[2 * (TP2 * 2)]);
            float2 v3 = bcast(tcol[3 * (TP2 * 2)]);
            float2 v4 = bcast(tcol[4 * (TP2 * 2)]);
            float2 v5 = bcast(tcol[5 * (TP2 * 2)]);

            const int  gox = ox0 + ox;
            const bool xok = (gox < OUT_W);

            #pragma unroll
            for (int j = 0; j < 16; j++) {
                float2 acc = fmul2(v0, c0);
                acc = ffma2(v1, c1, acc);
                acc = ffma2(v2, c2, acc);
                acc = ffma2(v3, c3, acc);
                acc = ffma2(v4, c4, acc);
                acc = ffma2(v5, c5, acc);
                const int goy = oy0 + 2 * (j0 + j);
                if (xok) {
                    o_img[(size_t)goy * OUT_W + gox] = acc.x;  // goy <= 510
                    if (goy + 1 < OUT_H)
                        o_img[(size_t)(goy + 1) * OUT_W + gox] = acc.y;
                }
                v0 = v1; v1 = v2; v2 = v3; v3 = v4; v4 = v5;
                if (j < 15) v5 = bcast(tcol[(j + 6) * (TP2 * 2)]); // row <= 36
            }
        }
        // Protect s_tmp (next horiz) before starting the next tile.
        if (t + 1 < TILES_Y) __syncthreads();
    }
}

extern "C" void kernel_launch(void* const* d_in, const int* in_sizes, int n_in,
                              void* d_out, int out_size) {
    const float* x = (const float*)d_in[0];   // [8,64,256,256] f32
    const float* K = (const float*)d_in[1];   // [12,12] f32
    float* out = (float*)d_out;               // [8,64,511,511] f32

    int imgs = in_sizes[0] / (IMG_H * IMG_W); // 512
    dim3 grid((OUT_W + TILE_W - 1) / TILE_W,  // 4
              (OUT_H + TILE_H * TILES_Y - 1) / (TILE_H * TILES_Y),  // 2
              imgs);                          // 512
    lpf_up2_kernel<<<grid, NTHR>>>(x, K, out);
}

// round 14
// speedup vs baseline: 1.5594x; 1.2933x over previous
#include <cuda_runtime.h>

// upfirdn2d(up=2, down=1, pad=5), 12x12 separable K = h h^T, via fma.rn.f32x2.
// R8 skeleton (best: 114us): 128x64 tile, 256 threads, parity-pair outputs,
// broadcast-input FFMA2, sliding register windows, idx-based load loop.
// R13: identical structure; base-pointer + immediate-offset STG, and
// streaming stores (st.global.cs) so 534MB of writes don't evict the
// L2-resident input.

#define IMG_H 256
#define IMG_W 256
#define OUT_H 511
#define OUT_W 511
#define TILE_W 128
#define TILE_H 64
#define IN_W  69      // input cols per 128-wide output tile
#define IN_H  37      // input rows per 64-tall output tile
#define SPITCH 69     // stride mod 32 = 5 -> conflict-free s_in column reads
#define TP2   65      // float2 pitch for tmp rows (130 floats)
#define NTHR  256

__device__ __forceinline__ float2 ffma2(float2 a, float2 b, float2 c) {
    float2 d;
    asm("fma.rn.f32x2 %0, %1, %2, %3;"
        : "=l"(*reinterpret_cast<unsigned long long*>(&d))
        : "l"(*reinterpret_cast<unsigned long long*>(&a)),
          "l"(*reinterpret_cast<unsigned long long*>(&b)),
          "l"(*reinterpret_cast<unsigned long long*>(&c)));
    return d;
}

__device__ __forceinline__ float2 fmul2(float2 a, float2 b) {
    float2 d;
    asm("mul.rn.f32x2 %0, %1, %2;"
        : "=l"(*reinterpret_cast<unsigned long long*>(&d))
        : "l"(*reinterpret_cast<unsigned long long*>(&a)),
          "l"(*reinterpret_cast<unsigned long long*>(&b)));
    return d;
}

__device__ __forceinline__ float2 bcast(float w) { return make_float2(w, w); }

__device__ __forceinline__ void stcs(float* p, float v) {
    asm volatile("st.global.cs.f32 [%0], %1;" :: "l"(p), "f"(v));
}

__global__ __launch_bounds__(NTHR)
void lpf_up2_kernel(const float* __restrict__ x,
                    const float* __restrict__ K,
                    float* __restrict__ out) {
    __shared__ float  s_in[IN_H * SPITCH];   // 37 x 69 input tile (zero-padded)
    __shared__ float2 s_tmp[IN_H * TP2];     // horiz result: 37 rows x 128 cols
    __shared__ float2 s_c[6];                // (h_even_tap[t], h_odd_tap[t])

    const int tid = threadIdx.x;
    const int img = blockIdx.z;
    const int ox0 = blockIdx.x * TILE_W;     // even
    const int oy0 = blockIdx.y * TILE_H;     // even
    const int mx0 = (ox0 >> 1) - 2;
    const int my0 = (oy0 >> 1) - 2;

    // Recover separable h from K row 5: h[j] = K[5][j] / sqrt(K[5][5]).
    // Sign ambiguity cancels (all taps are h*h products).
    if (tid < 6) {
        float s = rsqrtf(K[5 * 12 + 5]);
        s_c[tid] = make_float2(K[5 * 12 + (10 - 2 * tid)] * s,
                               K[5 * 12 + (11 - 2 * tid)] * s);
    }

    // ---- Load input tile (independent iterations -> high MLP) ----
    const float* __restrict__ xin = x + (size_t)img * (IMG_H * IMG_W);
    #pragma unroll
    for (int idx = tid; idx < IN_H * IN_W; idx += NTHR) {
        int r = idx / IN_W;
        int c = idx - r * IN_W;
        int gy = my0 + r;
        int gx = mx0 + c;
        float v = 0.0f;
        if ((unsigned)gy < IMG_H && (unsigned)gx < IMG_W)
            v = xin[gy * IMG_W + gx];
        s_in[r * SPITCH + c] = v;
    }
    __syncthreads();

    const float2 c0 = s_c[0], c1 = s_c[1], c2 = s_c[2],
                 c3 = s_c[3], c4 = s_c[4], c5 = s_c[5];

    // ---- Horizontal pass: tmp[r][pair k] = sum_t c[t]*s_in[r][k+t] ----
    // 37 rows x 8 groups of 8 pairs = 296 tasks; threads 0..39 take 2nd slot.
    #pragma unroll
    for (int tt = 0; tt < 2; tt++) {
        int t = tid + NTHR * tt;
        if (t < IN_H * 8) {
            int kg = t / IN_H;            // 0..7
            int r  = t - kg * IN_H;       // 0..36
            int k0 = kg * 8;
            const float* row = s_in + r * SPITCH + k0;
            float2* trow = s_tmp + r * TP2 + k0;
            float2 p0 = bcast(row[0]), p1 = bcast(row[1]),
                   p2 = bcast(row[2]), p3 = bcast(row[3]),
                   p4 = bcast(row[4]), p5 = bcast(row[5]);
            #pragma unroll
            for (int j = 0; j < 8; j++) {
                float2 acc = fmul2(p0, c0);
                acc = ffma2(p1, c1, acc);
                acc = ffma2(p2, c2, acc);
                acc = ffma2(p3, c3, acc);
                acc = ffma2(p4, c4, acc);
                acc = ffma2(p5, c5, acc);
                trow[j] = acc;
                p0 = p1; p1 = p2; p2 = p3; p3 = p4; p4 = p5;
                if (j < 7) p5 = bcast(row[j + 6]);   // max col = 56+7+6 = 68
            }
        }
    }
    __syncthreads();

    // ---- Vertical pass: out rows (2J, 2J+1) = sum_t c[t]*tmp[J+t][ox] ----
    // 128 columns x 2 groups of 16 row-pairs; broadcast pairs in registers.
    const int ox = tid & 127;
    const int j0 = (tid >> 7) * 16;     // 0 or 16
    const float* tcol = reinterpret_cast<const float*>(s_tmp) + j0 * (TP2 * 2) + ox;
    float2 v0 = bcast(tcol[0 * (TP2 * 2)]);
    float2 v1 = bcast(tcol[1 * (TP2 * 2)]);
    float2 v2 = bcast(tcol[2 * (TP2 * 2)]);
    float2 v3 = bcast(tcol[3 * (TP2 * 2)]);
    float2 v4 = bcast(tcol[4 * (TP2 * 2)]);
    float2 v5 = bcast(tcol[5 * (TP2 * 2)]);

    const int  gox = ox0 + ox;
    const bool xok = (gox < OUT_W);
    // Base pointer; per-j store offsets are compile-time immediates.
    float* __restrict__ p =
        out + (size_t)img * ((size_t)OUT_H * OUT_W) +
        (size_t)(oy0 + 2 * j0) * OUT_W + gox;
    // Only oy0=448, j0=16, j=15 would write row 511: skip it.
    const bool lastgrp = (oy0 + 2 * j0 == 480);

    #pragma unroll
    for (int j = 0; j < 16; j++) {
        float2 acc = fmul2(v0, c0);
        acc = ffma2(v1, c1, acc);
        acc = ffma2(v2, c2, acc);
        acc = ffma2(v3, c3, acc);
        acc = ffma2(v4, c4, acc);
        acc = ffma2(v5, c5, acc);
        if (xok) {
            stcs(p + (size_t)(2 * j) * OUT_W, acc.x);      // even row <= 510
            if (!lastgrp || j < 15)                         // skip row 511
                stcs(p + (size_t)(2 * j + 1) * OUT_W, acc.y);
        }
        v0 = v1; v1 = v2; v2 = v3; v3 = v4; v4 = v5;
        if (j < 15) v5 = bcast(tcol[(j + 6) * (TP2 * 2)]); // max row 16+14+6=36
    }
}

extern "C" void kernel_launch(void* const* d_in, const int* in_sizes, int n_in,
                              void* d_out, int out_size) {
    const float* x = (const float*)d_in[0];   // [8,64,256,256] f32
    const float* K = (const float*)d_in[1];   // [12,12] f32
    float* out = (float*)d_out;               // [8,64,511,511] f32

    int imgs = in_sizes[0] / (IMG_H * IMG_W); // 512
    dim3 grid((OUT_W + TILE_W - 1) / TILE_W,  // 4
              (OUT_H + TILE_H - 1) / TILE_H,  // 8
              imgs);                          // 512
    lpf_up2_kernel<<<grid, NTHR>>>(x, K, out);
}